// round 2
// baseline (speedup 1.0000x reference)
#include <cuda_runtime.h>

// LSTMOptimizer: per-element (N=524288) single LSTMCell step (input size 4,
// hidden H=128) + Linear(H,1) update head.
//
// Inputs (metadata order = reference signature order):
//  0 param[N] 1 grad[N] 2 h[N,H] 3 c[N,H] 4 momentum[N] 5 prev_update[N]
//  6 W_ih[4H,4] 7 W_hh[4H,H] 8 b_ih[4H] 9 b_hh[4H] 10 W_up[1,H] 11 b_up[1]
// Output: concat(update[N], h_new[N*H], c_new[N*H], momentum_new[N]) fp32.
//
// Strategy: one warp per element; lane owns 4 hidden columns. W_ih/bias/W_up
// hoisted to registers, amortized over a grid-stride loop. The h@W_hh.T term
// is only computed when the element's h row is nonzero (warp vote) — exact
// for h==0 (the structural case in setup_inputs: h is jnp.zeros), and fully
// correct via the generic shuffle-broadcast path otherwise. Memory-bound:
// ~1.04 GB of mandatory traffic.

namespace {

constexpr int HH = 128;

__device__ __forceinline__ float fsig(float z) {
    // sigmoid(z) = 1/(1+exp(-z)); __expf underflows/overflows safely here.
    return __frcp_rn(1.0f + __expf(-z));
}

__device__ __forceinline__ float ftanh(float z) {
    // tanh via exp, clamped so exp never produces inf (tanh(|z|>=15) == +-1 in fp32)
    float zc = fminf(fmaxf(z, -15.0f), 15.0f);
    float e  = __expf(2.0f * zc);
    return __fdividef(e - 1.0f, e + 1.0f);
}

__global__ void __launch_bounds__(256)
lstm_opt_kernel(const float* __restrict__ param, const float* __restrict__ grad,
                const float* __restrict__ hmat,  const float* __restrict__ cmat,
                const float* __restrict__ momentum, const float* __restrict__ prevu,
                const float* __restrict__ W_ih,  const float* __restrict__ W_hh,
                const float* __restrict__ b_ih,  const float* __restrict__ b_hh,
                const float* __restrict__ W_up,  const float* __restrict__ b_up,
                float* __restrict__ out_upd, float* __restrict__ out_h,
                float* __restrict__ out_c,   float* __restrict__ out_mom,
                int N)
{
    const int lane    = threadIdx.x & 31;
    const int warp    = blockIdx.x * (blockDim.x >> 5) + (threadIdx.x >> 5);
    const int nwarp   = gridDim.x * (blockDim.x >> 5);
    const int colbase = lane << 2;   // 4 hidden columns per lane

    // ---- hoist per-lane weights into registers (shared by all elements) ----
    float4 wih[4][4];   // [gate_group][k] : W_ih row (4 floats) for row g*128+colbase+k
    float  bsum[4][4];  // b_ih + b_hh for that row
    #pragma unroll
    for (int g = 0; g < 4; ++g) {
        #pragma unroll
        for (int k = 0; k < 4; ++k) {
            int r = g * HH + colbase + k;
            wih[g][k]  = __ldg(reinterpret_cast<const float4*>(W_ih + 4 * r));
            bsum[g][k] = __ldg(b_ih + r) + __ldg(b_hh + r);
        }
    }
    const float4 wup = __ldg(reinterpret_cast<const float4*>(W_up + colbase));
    const float  bup = __ldg(b_up);

    for (int e = warp; e < N; e += nwarp) {
        // scalar inputs (same address across warp -> broadcast)
        const float gv0 = __ldg(grad + e);
        const float pv0 = __ldg(param + e);
        const float mv0 = __ldg(momentum + e);
        const float uv0 = __ldg(prevu + e);

        const size_t rowoff = (size_t)e * HH + colbase;
        const float4 h4 = __ldg(reinterpret_cast<const float4*>(hmat + rowoff));
        const float4 c4 = __ldg(reinterpret_cast<const float4*>(cmat + rowoff));

        // gates z = W_ih @ x + (b_ih + b_hh)   (x = [grad, param, momentum, prev])
        float z[4][4];
        #pragma unroll
        for (int g = 0; g < 4; ++g) {
            #pragma unroll
            for (int k = 0; k < 4; ++k) {
                float zz = bsum[g][k];
                zz = fmaf(wih[g][k].x, gv0, zz);
                zz = fmaf(wih[g][k].y, pv0, zz);
                zz = fmaf(wih[g][k].z, mv0, zz);
                zz = fmaf(wih[g][k].w, uv0, zz);
                z[g][k] = zz;
            }
        }

        // recurrent term only if this element's h row is nonzero (exact skip)
        const bool hz = (h4.x != 0.0f) || (h4.y != 0.0f) || (h4.z != 0.0f) || (h4.w != 0.0f);
        if (__any_sync(0xffffffffu, hz)) {
            #pragma unroll 1
            for (int src = 0; src < 32; ++src) {
                const float b0 = __shfl_sync(0xffffffffu, h4.x, src);
                const float b1 = __shfl_sync(0xffffffffu, h4.y, src);
                const float b2 = __shfl_sync(0xffffffffu, h4.z, src);
                const float b3 = __shfl_sync(0xffffffffu, h4.w, src);
                const int kk = src << 2;
                #pragma unroll
                for (int g = 0; g < 4; ++g) {
                    #pragma unroll
                    for (int k = 0; k < 4; ++k) {
                        const float* wr = W_hh + (size_t)(g * HH + colbase + k) * HH + kk;
                        float zz = z[g][k];
                        zz = fmaf(__ldg(wr + 0), b0, zz);
                        zz = fmaf(__ldg(wr + 1), b1, zz);
                        zz = fmaf(__ldg(wr + 2), b2, zz);
                        zz = fmaf(__ldg(wr + 3), b3, zz);
                        z[g][k] = zz;
                    }
                }
            }
        }

        // activations + cell/hidden update + head partial dot
        const float cin[4] = {c4.x, c4.y, c4.z, c4.w};
        const float wuk[4] = {wup.x, wup.y, wup.z, wup.w};
        float hn[4], cn[4];
        float acc = 0.0f;
        #pragma unroll
        for (int k = 0; k < 4; ++k) {
            const float iv = fsig(z[0][k]);
            const float fv = fsig(z[1][k]);
            const float gg = ftanh(z[2][k]);
            const float ov = fsig(z[3][k]);
            const float cc = fmaf(fv, cin[k], iv * gg);
            const float hh = ov * ftanh(cc);
            cn[k] = cc;
            hn[k] = hh;
            acc = fmaf(hh, wuk[k], acc);
        }

        if (out_h != nullptr) {
            *reinterpret_cast<float4*>(out_h + rowoff) = make_float4(hn[0], hn[1], hn[2], hn[3]);
            *reinterpret_cast<float4*>(out_c + rowoff) = make_float4(cn[0], cn[1], cn[2], cn[3]);
        }

        // warp-reduce the update head
        #pragma unroll
        for (int off = 16; off; off >>= 1)
            acc += __shfl_xor_sync(0xffffffffu, acc, off);

        if (lane == 0) {
            const float upd = acc + bup;
            out_upd[e] = upd;
            if (out_mom != nullptr) out_mom[e] = fmaf(0.9f, mv0, upd);
        }
    }
}

}  // namespace

extern "C" void kernel_launch(void* const* d_in, const int* in_sizes, int n_in,
                              void* d_out, int out_size) {
    const float* param = (const float*)d_in[0];
    const float* grad  = (const float*)d_in[1];
    const float* h     = (const float*)d_in[2];
    const float* c     = (const float*)d_in[3];
    const float* mom   = (const float*)d_in[4];
    const float* prevu = (const float*)d_in[5];
    const float* W_ih  = (const float*)d_in[6];
    const float* W_hh  = (const float*)d_in[7];
    const float* b_ih  = (const float*)d_in[8];
    const float* b_hh  = (const float*)d_in[9];
    const float* W_up  = (const float*)d_in[10];
    const float* b_up  = (const float*)d_in[11];

    const int N = in_sizes[0];
    float* out = (float*)d_out;

    // Output layout: concat(update, h_new, c_new, momentum_new) in reference
    // return order; degrade gracefully if harness only wants a prefix.
    float* out_upd = out;
    float* out_h   = nullptr;
    float* out_c   = nullptr;
    float* out_mom = nullptr;
    const long long full = 2LL * N + 2LL * N * 128;
    if ((long long)out_size >= full) {
        out_h   = out + N;
        out_c   = out + N + (size_t)N * 128;
        out_mom = out + N + 2 * (size_t)N * 128;
    } else if (out_size >= 2 * N) {
        out_mom = out + N;  // update + momentum only
    }

    const int threads = 256;
    const int blocks  = 1184;  // 148 SMs * 8 blocks, grid-stride over elements
    lstm_opt_kernel<<<blocks, threads>>>(param, grad, h, c, mom, prevu,
                                         W_ih, W_hh, b_ih, b_hh, W_up, b_up,
                                         out_upd, out_h, out_c, out_mom, N);
}

// round 5
// speedup vs baseline: 1.2648x; 1.2648x over previous
#include <cuda_runtime.h>

// LSTMOptimizer: per-element (N=524288) single LSTMCell step (input 4, H=128)
// + Linear(H,1) head. One warp per element-pair; lane owns 4 hidden columns.
//
// R4: same theory as R2/R3 (which hit infra failures twice), with the inline
// f32x2 asm removed as a risk hedge:
//  - W_ih/bias in a conflict-free SMEM table (float4[32][21]) instead of regs
//  - tanh.approx.f32 (MUFU.TANH) activations
//  - two elements per loop iteration (weight-read amortization + 2x MLP)
//  - plain scalar FMA for the gate GEMV (fma pipe was only 23% in R1)

namespace {

constexpr int HH = 128;
constexpr int WSLOTS = 21;  // float4 slots per lane: 16 W rows + 4 bias + 1 wup

__device__ __forceinline__ float tanhx(float x) {
    float y;
    asm("tanh.approx.f32 %0, %1;" : "=f"(y) : "f"(x));
    return y;
}
__device__ __forceinline__ float sigx(float z) {
    return fmaf(0.5f, tanhx(0.5f * z), 0.5f);
}

// Generic recurrent term (h != 0): exact shuffle-broadcast h @ W_hh.T.
// Warp-uniform entry (guarded by __any_sync result). Rare path.
__device__ __noinline__ void add_recurrent(float zf[16], float4 h4,
                                           const float* __restrict__ W_hh,
                                           int colbase) {
    #pragma unroll 1
    for (int src = 0; src < 32; ++src) {
        const float b0 = __shfl_sync(0xffffffffu, h4.x, src);
        const float b1 = __shfl_sync(0xffffffffu, h4.y, src);
        const float b2 = __shfl_sync(0xffffffffu, h4.z, src);
        const float b3 = __shfl_sync(0xffffffffu, h4.w, src);
        const int kk = src << 2;
        #pragma unroll
        for (int g = 0; g < 4; ++g) {
            #pragma unroll
            for (int k = 0; k < 4; ++k) {
                const float* wr = W_hh + (size_t)(g * HH + colbase + k) * HH + kk;
                float zz = zf[g * 4 + k];
                zz = fmaf(__ldg(wr + 0), b0, zz);
                zz = fmaf(__ldg(wr + 1), b1, zz);
                zz = fmaf(__ldg(wr + 2), b2, zz);
                zz = fmaf(__ldg(wr + 3), b3, zz);
                zf[g * 4 + k] = zz;
            }
        }
    }
}

// Activations + cell/hidden update + head partial dot for one element.
__device__ __forceinline__ float finish_elem(const float zf[16], float4 c4,
                                             float4 wup, float4& hn4, float4& cn4) {
    const float cin[4] = {c4.x, c4.y, c4.z, c4.w};
    const float wuk[4] = {wup.x, wup.y, wup.z, wup.w};
    float hn[4], cn[4];
    float acc = 0.0f;
    #pragma unroll
    for (int k = 0; k < 4; ++k) {
        const float iv = sigx(zf[0 * 4 + k]);
        const float fv = sigx(zf[1 * 4 + k]);
        const float gg = tanhx(zf[2 * 4 + k]);
        const float ov = sigx(zf[3 * 4 + k]);
        const float cc = fmaf(fv, cin[k], iv * gg);
        const float hh = ov * tanhx(cc);
        cn[k] = cc;
        hn[k] = hh;
        acc = fmaf(hh, wuk[k], acc);
    }
    hn4 = make_float4(hn[0], hn[1], hn[2], hn[3]);
    cn4 = make_float4(cn[0], cn[1], cn[2], cn[3]);
    return acc;
}

__global__ void __launch_bounds__(128)
lstm_opt_kernel(const float* __restrict__ param, const float* __restrict__ grad,
                const float* __restrict__ hmat,  const float* __restrict__ cmat,
                const float* __restrict__ momentum, const float* __restrict__ prevu,
                const float* __restrict__ W_ih,  const float* __restrict__ W_hh,
                const float* __restrict__ b_ih,  const float* __restrict__ b_hh,
                const float* __restrict__ W_up,  const float* __restrict__ b_up,
                float* __restrict__ out_upd, float* __restrict__ out_h,
                float* __restrict__ out_c,   float* __restrict__ out_mom,
                int N)
{
    // Per-lane table (float4 slots):
    //   [0..15]  W_ih row (4 floats) for gate-row r = (q>>2)*128 + lane*4 + (q&3)
    //   [16..19] bias sums b_ih[r]+b_hh[r] for the 16 rows (4 per slot)
    //   [20]     W_up[lane*4 .. +3]
    // Lane stride 21 slots (336B): conflict-free for LDS.128 at fixed q.
    __shared__ float4 wtab[32 * WSLOTS];

    for (int idx = threadIdx.x; idx < 32 * WSLOTS; idx += blockDim.x) {
        const int l = idx / WSLOTS;
        const int q = idx % WSLOTS;
        float4 v;
        if (q < 16) {
            const int r = (q >> 2) * HH + l * 4 + (q & 3);
            v = *reinterpret_cast<const float4*>(W_ih + 4 * r);
        } else if (q < 20) {
            const int g = q - 16;
            const int r0 = g * HH + l * 4;
            v = make_float4(b_ih[r0 + 0] + b_hh[r0 + 0],
                            b_ih[r0 + 1] + b_hh[r0 + 1],
                            b_ih[r0 + 2] + b_hh[r0 + 2],
                            b_ih[r0 + 3] + b_hh[r0 + 3]);
        } else {
            v = *reinterpret_cast<const float4*>(W_up + l * 4);
        }
        wtab[idx] = v;
    }
    __syncthreads();

    const int lane    = threadIdx.x & 31;
    const int warp    = blockIdx.x * (blockDim.x >> 5) + (threadIdx.x >> 5);
    const int nwarp   = gridDim.x * (blockDim.x >> 5);
    const int colbase = lane << 2;
    const float4* wl  = wtab + lane * WSLOTS;

    const float4 wup = wl[20];
    const float  bup = __ldg(b_up);

    for (int ea = warp; ea < N; ea += 2 * nwarp) {
        const int  eb   = ea + nwarp;
        const bool hasb = (eb < N);

        // ---- front-batched loads: independent 512B/warp loads + scalars ----
        const size_t rowa = (size_t)ea * HH + colbase;
        const float4 h4a = __ldg(reinterpret_cast<const float4*>(hmat + rowa));
        const float4 c4a = __ldg(reinterpret_cast<const float4*>(cmat + rowa));
        const float  gva = __ldg(grad + ea);
        const float  pva = __ldg(param + ea);
        const float  mva = __ldg(momentum + ea);
        const float  uva = __ldg(prevu + ea);

        const size_t rowb = hasb ? (size_t)eb * HH + colbase : rowa;
        const float4 h4b = __ldg(reinterpret_cast<const float4*>(hmat + rowb));
        const float4 c4b = __ldg(reinterpret_cast<const float4*>(cmat + rowb));
        const float  gvb = hasb ? __ldg(grad + eb) : 0.0f;
        const float  pvb = hasb ? __ldg(param + eb) : 0.0f;
        const float  mvb = hasb ? __ldg(momentum + eb) : 0.0f;
        const float  uvb = hasb ? __ldg(prevu + eb) : 0.0f;

        // ---- gates: z = bs + W_ih @ x ; weights read once for both elems ----
        float za[16], zb[16];
        #pragma unroll
        for (int g = 0; g < 4; ++g) {
            const float4 bs = wl[16 + g];
            const float bsk[4] = {bs.x, bs.y, bs.z, bs.w};
            #pragma unroll
            for (int k = 0; k < 4; ++k) {
                const float4 w = wl[g * 4 + k];
                float z = bsk[k];
                z = fmaf(w.x, gva, z);
                z = fmaf(w.y, pva, z);
                z = fmaf(w.z, mva, z);
                z = fmaf(w.w, uva, z);
                za[g * 4 + k] = z;
                z = bsk[k];
                z = fmaf(w.x, gvb, z);
                z = fmaf(w.y, pvb, z);
                z = fmaf(w.z, mvb, z);
                z = fmaf(w.w, uvb, z);
                zb[g * 4 + k] = z;
            }
        }

        // ---- element A ----
        {
            const bool hz = (h4a.x != 0.0f) || (h4a.y != 0.0f) ||
                            (h4a.z != 0.0f) || (h4a.w != 0.0f);
            if (__any_sync(0xffffffffu, hz))
                add_recurrent(za, h4a, W_hh, colbase);

            float4 hn4, cn4;
            float acc = finish_elem(za, c4a, wup, hn4, cn4);
            if (out_h != nullptr) {
                *reinterpret_cast<float4*>(out_h + rowa) = hn4;
                *reinterpret_cast<float4*>(out_c + rowa) = cn4;
            }
            #pragma unroll
            for (int off = 16; off; off >>= 1)
                acc += __shfl_xor_sync(0xffffffffu, acc, off);
            if (lane == 0) {
                const float upd = acc + bup;
                out_upd[ea] = upd;
                if (out_mom != nullptr) out_mom[ea] = fmaf(0.9f, mva, upd);
            }
        }

        // ---- element B ----
        if (hasb) {
            const bool hz = (h4b.x != 0.0f) || (h4b.y != 0.0f) ||
                            (h4b.z != 0.0f) || (h4b.w != 0.0f);
            if (__any_sync(0xffffffffu, hz))
                add_recurrent(zb, h4b, W_hh, colbase);

            float4 hn4, cn4;
            float acc = finish_elem(zb, c4b, wup, hn4, cn4);
            if (out_h != nullptr) {
                *reinterpret_cast<float4*>(out_h + rowb) = hn4;
                *reinterpret_cast<float4*>(out_c + rowb) = cn4;
            }
            #pragma unroll
            for (int off = 16; off; off >>= 1)
                acc += __shfl_xor_sync(0xffffffffu, acc, off);
            if (lane == 0) {
                const float upd = acc + bup;
                out_upd[eb] = upd;
                if (out_mom != nullptr) out_mom[eb] = fmaf(0.9f, mvb, upd);
            }
        }
    }
}

}  // namespace

extern "C" void kernel_launch(void* const* d_in, const int* in_sizes, int n_in,
                              void* d_out, int out_size) {
    const float* param = (const float*)d_in[0];
    const float* grad  = (const float*)d_in[1];
    const float* h     = (const float*)d_in[2];
    const float* c     = (const float*)d_in[3];
    const float* mom   = (const float*)d_in[4];
    const float* prevu = (const float*)d_in[5];
    const float* W_ih  = (const float*)d_in[6];
    const float* W_hh  = (const float*)d_in[7];
    const float* b_ih  = (const float*)d_in[8];
    const float* b_hh  = (const float*)d_in[9];
    const float* W_up  = (const float*)d_in[10];
    const float* b_up  = (const float*)d_in[11];

    const int N = in_sizes[0];
    float* out = (float*)d_out;

    // Output layout: concat(update, h_new, c_new, momentum_new), reference order.
    float* out_upd = out;
    float* out_h   = nullptr;
    float* out_c   = nullptr;
    float* out_mom = nullptr;
    const long long full = 2LL * N + 2LL * N * 128;
    if ((long long)out_size >= full) {
        out_h   = out + N;
        out_c   = out + N + (size_t)N * 128;
        out_mom = out + N + 2 * (size_t)N * 128;
    } else if (out_size >= 2 * N) {
        out_mom = out + N;
    }

    const int threads = 128;
    const int blocks  = 1184;  // grid-stride; 148 SMs
    lstm_opt_kernel<<<blocks, threads>>>(param, grad, h, c, mom, prevu,
                                         W_ih, W_hh, b_ih, b_hh, W_up, b_up,
                                         out_upd, out_h, out_c, out_mom, N);
}

// round 6
// speedup vs baseline: 1.6517x; 1.3059x over previous
#include <cuda_runtime.h>

// LSTMOptimizer: per-element (N=524288) single LSTMCell step (input 4, H=128)
// + Linear(H,1) head. One warp per element-pair; lane owns 4 hidden columns.
//
// R5 vs R4 (348us, latency-bound: occ 31%, DRAM 38%, issue 32%):
//  - __launch_bounds__(128,7): regs 80 -> <=72, 7 blocks/SM resident (occ ~43%)
//  - grid 1024 blocks (nwarp=4096): N divides 2*nwarp exactly -> guard-free
//    main loop, single clean wave; generic tail loop retained (empty here)
//  - streaming cache ops: __ldcs on h/c rows (read-once), __stcs on h/c out
//    rows (write-once) to stop the 1GB stream thrashing L2

namespace {

constexpr int HH = 128;
constexpr int WSLOTS = 21;  // float4 slots per lane: 16 W rows + 4 bias + 1 wup

__device__ __forceinline__ float tanhx(float x) {
    float y;
    asm("tanh.approx.f32 %0, %1;" : "=f"(y) : "f"(x));
    return y;
}
__device__ __forceinline__ float sigx(float z) {
    return fmaf(0.5f, tanhx(0.5f * z), 0.5f);
}

// Generic recurrent term (h != 0): exact shuffle-broadcast h @ W_hh.T.
// Warp-uniform entry (guarded by __any_sync result). Rare path.
__device__ __noinline__ void add_recurrent(float zf[16], float4 h4,
                                           const float* __restrict__ W_hh,
                                           int colbase) {
    #pragma unroll 1
    for (int src = 0; src < 32; ++src) {
        const float b0 = __shfl_sync(0xffffffffu, h4.x, src);
        const float b1 = __shfl_sync(0xffffffffu, h4.y, src);
        const float b2 = __shfl_sync(0xffffffffu, h4.z, src);
        const float b3 = __shfl_sync(0xffffffffu, h4.w, src);
        const int kk = src << 2;
        #pragma unroll
        for (int g = 0; g < 4; ++g) {
            #pragma unroll
            for (int k = 0; k < 4; ++k) {
                const float* wr = W_hh + (size_t)(g * HH + colbase + k) * HH + kk;
                float zz = zf[g * 4 + k];
                zz = fmaf(__ldg(wr + 0), b0, zz);
                zz = fmaf(__ldg(wr + 1), b1, zz);
                zz = fmaf(__ldg(wr + 2), b2, zz);
                zz = fmaf(__ldg(wr + 3), b3, zz);
                zf[g * 4 + k] = zz;
            }
        }
    }
}

// Activations + cell/hidden update + head partial dot for one element.
__device__ __forceinline__ float finish_elem(const float zf[16], float4 c4,
                                             float4 wup, float4& hn4, float4& cn4) {
    const float cin[4] = {c4.x, c4.y, c4.z, c4.w};
    const float wuk[4] = {wup.x, wup.y, wup.z, wup.w};
    float hn[4], cn[4];
    float acc = 0.0f;
    #pragma unroll
    for (int k = 0; k < 4; ++k) {
        const float iv = sigx(zf[0 * 4 + k]);
        const float fv = sigx(zf[1 * 4 + k]);
        const float gg = tanhx(zf[2 * 4 + k]);
        const float ov = sigx(zf[3 * 4 + k]);
        const float cc = fmaf(fv, cin[k], iv * gg);
        const float hh = ov * tanhx(cc);
        cn[k] = cc;
        hn[k] = hh;
        acc = fmaf(hh, wuk[k], acc);
    }
    hn4 = make_float4(hn[0], hn[1], hn[2], hn[3]);
    cn4 = make_float4(cn[0], cn[1], cn[2], cn[3]);
    return acc;
}

__global__ void __launch_bounds__(128, 7)
lstm_opt_kernel(const float* __restrict__ param, const float* __restrict__ grad,
                const float* __restrict__ hmat,  const float* __restrict__ cmat,
                const float* __restrict__ momentum, const float* __restrict__ prevu,
                const float* __restrict__ W_ih,  const float* __restrict__ W_hh,
                const float* __restrict__ b_ih,  const float* __restrict__ b_hh,
                const float* __restrict__ W_up,  const float* __restrict__ b_up,
                float* __restrict__ out_upd, float* __restrict__ out_h,
                float* __restrict__ out_c,   float* __restrict__ out_mom,
                int N)
{
    // Per-lane table (float4 slots):
    //   [0..15]  W_ih row (4 floats) for gate-row r = (q>>2)*128 + lane*4 + (q&3)
    //   [16..19] bias sums b_ih[r]+b_hh[r] for the 16 rows (4 per slot)
    //   [20]     W_up[lane*4 .. +3]
    __shared__ float4 wtab[32 * WSLOTS];

    for (int idx = threadIdx.x; idx < 32 * WSLOTS; idx += blockDim.x) {
        const int l = idx / WSLOTS;
        const int q = idx % WSLOTS;
        float4 v;
        if (q < 16) {
            const int r = (q >> 2) * HH + l * 4 + (q & 3);
            v = *reinterpret_cast<const float4*>(W_ih + 4 * r);
        } else if (q < 20) {
            const int g = q - 16;
            const int r0 = g * HH + l * 4;
            v = make_float4(b_ih[r0 + 0] + b_hh[r0 + 0],
                            b_ih[r0 + 1] + b_hh[r0 + 1],
                            b_ih[r0 + 2] + b_hh[r0 + 2],
                            b_ih[r0 + 3] + b_hh[r0 + 3]);
        } else {
            v = *reinterpret_cast<const float4*>(W_up + l * 4);
        }
        wtab[idx] = v;
    }
    __syncthreads();

    const int lane    = threadIdx.x & 31;
    const int warp    = blockIdx.x * (blockDim.x >> 5) + (threadIdx.x >> 5);
    const int nwarp   = gridDim.x * (blockDim.x >> 5);
    const int colbase = lane << 2;
    const float4* wl  = wtab + lane * WSLOTS;

    const float4 wup = wl[20];
    const float  bup = __ldg(b_up);

    // Main loop: guard-free; host picks grid so N % (2*nwarp)==0 for this N.
    const int iters = N / (2 * nwarp);
    int ea = warp;
    for (int it = 0; it < iters; ++it, ea += 2 * nwarp) {
        const int eb = ea + nwarp;

        // ---- front-batched loads: independent 512B/warp loads + scalars ----
        const size_t rowa = (size_t)ea * HH + colbase;
        const float4 h4a = __ldcs(reinterpret_cast<const float4*>(hmat + rowa));
        const float4 c4a = __ldcs(reinterpret_cast<const float4*>(cmat + rowa));
        const float  gva = __ldg(grad + ea);
        const float  pva = __ldg(param + ea);
        const float  mva = __ldg(momentum + ea);
        const float  uva = __ldg(prevu + ea);

        const size_t rowb = (size_t)eb * HH + colbase;
        const float4 h4b = __ldcs(reinterpret_cast<const float4*>(hmat + rowb));
        const float4 c4b = __ldcs(reinterpret_cast<const float4*>(cmat + rowb));
        const float  gvb = __ldg(grad + eb);
        const float  pvb = __ldg(param + eb);
        const float  mvb = __ldg(momentum + eb);
        const float  uvb = __ldg(prevu + eb);

        // ---- gates: z = bs + W_ih @ x ; weights read once for both elems ----
        float za[16], zb[16];
        #pragma unroll
        for (int g = 0; g < 4; ++g) {
            const float4 bs = wl[16 + g];
            const float bsk[4] = {bs.x, bs.y, bs.z, bs.w};
            #pragma unroll
            for (int k = 0; k < 4; ++k) {
                const float4 w = wl[g * 4 + k];
                float z = bsk[k];
                z = fmaf(w.x, gva, z);
                z = fmaf(w.y, pva, z);
                z = fmaf(w.z, mva, z);
                z = fmaf(w.w, uva, z);
                za[g * 4 + k] = z;
                z = bsk[k];
                z = fmaf(w.x, gvb, z);
                z = fmaf(w.y, pvb, z);
                z = fmaf(w.z, mvb, z);
                z = fmaf(w.w, uvb, z);
                zb[g * 4 + k] = z;
            }
        }

        // ---- element A ----
        {
            const bool hz = (h4a.x != 0.0f) || (h4a.y != 0.0f) ||
                            (h4a.z != 0.0f) || (h4a.w != 0.0f);
            if (__any_sync(0xffffffffu, hz))
                add_recurrent(za, h4a, W_hh, colbase);

            float4 hn4, cn4;
            float acc = finish_elem(za, c4a, wup, hn4, cn4);
            if (out_h != nullptr) {
                __stcs(reinterpret_cast<float4*>(out_h + rowa), hn4);
                __stcs(reinterpret_cast<float4*>(out_c + rowa), cn4);
            }
            #pragma unroll
            for (int off = 16; off; off >>= 1)
                acc += __shfl_xor_sync(0xffffffffu, acc, off);
            if (lane == 0) {
                const float upd = acc + bup;
                out_upd[ea] = upd;
                if (out_mom != nullptr) out_mom[ea] = fmaf(0.9f, mva, upd);
            }
        }

        // ---- element B ----
        {
            const bool hz = (h4b.x != 0.0f) || (h4b.y != 0.0f) ||
                            (h4b.z != 0.0f) || (h4b.w != 0.0f);
            if (__any_sync(0xffffffffu, hz))
                add_recurrent(zb, h4b, W_hh, colbase);

            float4 hn4, cn4;
            float acc = finish_elem(zb, c4b, wup, hn4, cn4);
            if (out_h != nullptr) {
                __stcs(reinterpret_cast<float4*>(out_h + rowb), hn4);
                __stcs(reinterpret_cast<float4*>(out_c + rowb), cn4);
            }
            #pragma unroll
            for (int off = 16; off; off >>= 1)
                acc += __shfl_xor_sync(0xffffffffu, acc, off);
            if (lane == 0) {
                const float upd = acc + bup;
                out_upd[eb] = upd;
                if (out_mom != nullptr) out_mom[eb] = fmaf(0.9f, mvb, upd);
            }
        }
    }

    // Generic tail (empty when N % (2*nwarp) == 0).
    for (int e = warp + iters * 2 * nwarp; e < N; e += nwarp) {
        const size_t row = (size_t)e * HH + colbase;
        const float4 h4 = __ldcs(reinterpret_cast<const float4*>(hmat + row));
        const float4 c4 = __ldcs(reinterpret_cast<const float4*>(cmat + row));
        const float  gv = __ldg(grad + e);
        const float  pv = __ldg(param + e);
        const float  mv = __ldg(momentum + e);
        const float  uv = __ldg(prevu + e);

        float zf[16];
        #pragma unroll
        for (int g = 0; g < 4; ++g) {
            const float4 bs = wl[16 + g];
            const float bsk[4] = {bs.x, bs.y, bs.z, bs.w};
            #pragma unroll
            for (int k = 0; k < 4; ++k) {
                const float4 w = wl[g * 4 + k];
                float z = bsk[k];
                z = fmaf(w.x, gv, z);
                z = fmaf(w.y, pv, z);
                z = fmaf(w.z, mv, z);
                z = fmaf(w.w, uv, z);
                zf[g * 4 + k] = z;
            }
        }
        const bool hz = (h4.x != 0.0f) || (h4.y != 0.0f) ||
                        (h4.z != 0.0f) || (h4.w != 0.0f);
        if (__any_sync(0xffffffffu, hz))
            add_recurrent(zf, h4, W_hh, colbase);

        float4 hn4, cn4;
        float acc = finish_elem(zf, c4, wup, hn4, cn4);
        if (out_h != nullptr) {
            __stcs(reinterpret_cast<float4*>(out_h + row), hn4);
            __stcs(reinterpret_cast<float4*>(out_c + row), cn4);
        }
        #pragma unroll
        for (int off = 16; off; off >>= 1)
            acc += __shfl_xor_sync(0xffffffffu, acc, off);
        if (lane == 0) {
            const float upd = acc + bup;
            out_upd[e] = upd;
            if (out_mom != nullptr) out_mom[e] = fmaf(0.9f, mv, upd);
        }
    }
}

}  // namespace

extern "C" void kernel_launch(void* const* d_in, const int* in_sizes, int n_in,
                              void* d_out, int out_size) {
    const float* param = (const float*)d_in[0];
    const float* grad  = (const float*)d_in[1];
    const float* h     = (const float*)d_in[2];
    const float* c     = (const float*)d_in[3];
    const float* mom   = (const float*)d_in[4];
    const float* prevu = (const float*)d_in[5];
    const float* W_ih  = (const float*)d_in[6];
    const float* W_hh  = (const float*)d_in[7];
    const float* b_ih  = (const float*)d_in[8];
    const float* b_hh  = (const float*)d_in[9];
    const float* W_up  = (const float*)d_in[10];
    const float* b_up  = (const float*)d_in[11];

    const int N = in_sizes[0];
    float* out = (float*)d_out;

    // Output layout: concat(update, h_new, c_new, momentum_new), reference order.
    float* out_upd = out;
    float* out_h   = nullptr;
    float* out_c   = nullptr;
    float* out_mom = nullptr;
    const long long full = 2LL * N + 2LL * N * 128;
    if ((long long)out_size >= full) {
        out_h   = out + N;
        out_c   = out + N + (size_t)N * 128;
        out_mom = out + N + 2 * (size_t)N * 128;
    } else if (out_size >= 2 * N) {
        out_mom = out + N;
    }

    // 1024 blocks * 4 warps = 4096 warps: N=2^19 % (2*4096) == 0 -> guard-free
    // main loop; 1024 <= 148 SMs * 7 resident -> single wave.
    const int threads = 128;
    const int blocks  = 1024;
    lstm_opt_kernel<<<blocks, threads>>>(param, grad, h, c, mom, prevu,
                                         W_ih, W_hh, b_ih, b_hh, W_up, b_up,
                                         out_upd, out_h, out_c, out_mom, N);
}